// round 17
// baseline (speedup 1.0000x reference)
#include <cuda_runtime.h>
#include <cuda_bf16.h>
#include <math_constants.h>
#include <cstdint>

#define BATCH 2
#define N1 4096
#define N2 32768
#define C1 128
#define C2 64
#define F1 128
#define F2 128
#define IN0S 131   // 3 + C1
#define IN1S 67    // 3 + C2
#define KEPS 1e-7f

#define HST 136    // sH fp32 row stride (floats)
#define ASTB 72    // bf16 row stride for A / W1bT (36 banks, ≡4 mod 32)
#define HSTB 136   // bf16 row stride for H / W2T  (68 banks, ≡4 mod 32)

#define NSLICE 4               // knn candidate-dim split
#define CPT (N1 / NSLICE)      // 1024 candidates per slice

// ---- mlp smem byte map ----------------------------------------------------
#define SH_B    0          // sH fp32: 128*136*4 = 69632   (aliased by H bf16)
#define HHI_B   0          // H hi bf16: 128*136*2 = 34816
#define HLO_B   34816      // H lo bf16: 34816
#define AHI_B   69632      // A hi bf16: 128*72*2 = 18432
#define ALO_B   88064
#define W1HI_B  106496     // W1b^T hi bf16 (n,k): 18432
#define W1LO_B  124928
#define W2HI_B  143360     // W2^T hi bf16 (n,k): 34816
#define W2LO_B  178176
#define B1_B    212992     // 128 floats
#define B2_B    213504     // 128 floats
#define MLP_SMEM_B 214016

// Scratch (static device globals: allocation-free)
__device__ float g_PW[BATCH * N1 * F1];          // points1 @ W1[0:128,:]
__device__ int   g_idx[BATCH * N2 * 3];
__device__ float g_w[BATCH * N2 * 3];
__device__ float g_pd[BATCH * N2 * NSLICE * 3];
__device__ int   g_pi[BATCH * N2 * NSLICE * 3];

#define TOP3_UPDATE(d, e0, e1, e2, i0, i1, i2, j)              \
    if ((d) < (e2)) {                                          \
        if ((d) < (e1)) {                                      \
            (e2) = (e1); (i2) = (i1);                          \
            if ((d) < (e0)) { (e1) = (e0); (i1) = (i0);        \
                              (e0) = (d);  (i0) = (j); }       \
            else            { (e1) = (d);  (i1) = (j); }       \
        } else { (e2) = (d); (i2) = (j); }                     \
    }

// bf16 warp MMA: D(16x8) += A(16x16,row) * B(16x8,col)  — base-target PTX
#define MMA_BF16(c, a0, a1, a2, a3, b0, b1)                                   \
    asm volatile(                                                             \
        "mma.sync.aligned.m16n8k16.row.col.f32.bf16.bf16.f32 "                \
        "{%0,%1,%2,%3}, {%4,%5,%6,%7}, {%8,%9}, {%0,%1,%2,%3};"               \
        : "+f"((c)[0]), "+f"((c)[1]), "+f"((c)[2]), "+f"((c)[3])              \
        : "r"(a0), "r"(a1), "r"(a2), "r"(a3), "r"(b0), "r"(b1))

__device__ __forceinline__ uint32_t pack_bf16_hi2(float x, float y,
                                                  uint32_t* lo) {
    __nv_bfloat16 hx = __float2bfloat16(x);
    __nv_bfloat16 hy = __float2bfloat16(y);
    __nv_bfloat16 lx = __float2bfloat16(x - __bfloat162float(hx));
    __nv_bfloat16 ly = __float2bfloat16(y - __bfloat162float(hy));
    *lo = (uint32_t)__bfloat16_as_ushort(lx)
        | ((uint32_t)__bfloat16_as_ushort(ly) << 16);
    return (uint32_t)__bfloat16_as_ushort(hx)
        | ((uint32_t)__bfloat16_as_ushort(hy) << 16);
}

// ---------------------------------------------------------------------------
// K0: PW = points1 @ W1[0:128,:]
// ---------------------------------------------------------------------------
__global__ void pw_kernel(const float* __restrict__ in0, const float* __restrict__ W1) {
    __shared__ float srow[8][128];
    int tid = threadIdx.x;
    long rowbase = (long)blockIdx.x * 8;
    #pragma unroll
    for (int r = 0; r < 8; r++)
        srow[r][tid] = in0[(rowbase + r) * IN0S + 3 + tid];
    __syncthreads();
    float acc[8];
    #pragma unroll
    for (int r = 0; r < 8; r++) acc[r] = 0.f;
    #pragma unroll 4
    for (int k = 0; k < 128; k++) {
        float w = __ldg(&W1[k * F1 + tid]);
        #pragma unroll
        for (int r = 0; r < 8; r++) acc[r] = fmaf(srow[r][k], w, acc[r]);
    }
    #pragma unroll
    for (int r = 0; r < 8; r++)
        g_PW[(rowbase + r) * F1 + tid] = acc[r];
}

// ---------------------------------------------------------------------------
// K1a: partial 3-NN (proven config: 2 queries/thread, NSLICE slices)
// ---------------------------------------------------------------------------
__global__ void knn_part_kernel(const float* __restrict__ in0,
                                const float* __restrict__ in1) {
    __shared__ float4 tile[CPT];
    int tid = threadIdx.x;
    int b  = blockIdx.z;
    int sl = blockIdx.y;
    int cs = sl * CPT;
    int qA = blockIdx.x * 512 + tid;
    int qB = qA + 256;
    int gA = b * N2 + qA;
    int gB = b * N2 + qB;

    const float* q = in1 + (size_t)gA * IN1S;
    float nAx = -2.f * q[0], nAy = -2.f * q[1], nAz = -2.f * q[2];
    q = in1 + (size_t)gB * IN1S;
    float nBx = -2.f * q[0], nBy = -2.f * q[1], nBz = -2.f * q[2];

    for (int s = tid; s < CPT; s += 256) {
        const float* p = in0 + (size_t)(b * N1 + cs + s) * IN0S;
        float px = p[0], py = p[1], pz = p[2];
        tile[s] = make_float4(px, py, pz, fmaf(px, px, fmaf(py, py, pz * pz)));
    }
    __syncthreads();

    float eA0 = CUDART_INF_F, eA1 = CUDART_INF_F, eA2 = CUDART_INF_F;
    float eB0 = CUDART_INF_F, eB1 = CUDART_INF_F, eB2 = CUDART_INF_F;
    int iA0 = 0, iA1 = 0, iA2 = 0, iB0 = 0, iB1 = 0, iB2 = 0;

    #pragma unroll 8
    for (int s = 0; s < CPT; s++) {
        float4 p = tile[s];
        float dA = fmaf(p.x, nAx, p.w);
        dA = fmaf(p.y, nAy, dA);
        dA = fmaf(p.z, nAz, dA);
        float dB = fmaf(p.x, nBx, p.w);
        dB = fmaf(p.y, nBy, dB);
        dB = fmaf(p.z, nBz, dB);
        int j = cs + s;
        TOP3_UPDATE(dA, eA0, eA1, eA2, iA0, iA1, iA2, j);
        TOP3_UPDATE(dB, eB0, eB1, eB2, iB0, iB1, iB2, j);
    }

    size_t oA = ((size_t)gA * NSLICE + sl) * 3;
    size_t oB = ((size_t)gB * NSLICE + sl) * 3;
    g_pd[oA + 0] = eA0; g_pd[oA + 1] = eA1; g_pd[oA + 2] = eA2;
    g_pi[oA + 0] = iA0; g_pi[oA + 1] = iA1; g_pi[oA + 2] = iA2;
    g_pd[oB + 0] = eB0; g_pd[oB + 1] = eB1; g_pd[oB + 2] = eB2;
    g_pi[oB + 0] = iB0; g_pi[oB + 1] = iB1; g_pi[oB + 2] = iB2;
}

// ---------------------------------------------------------------------------
// K1b: merge partials, exact-distance recompute, weights + xyz
// ---------------------------------------------------------------------------
__global__ void knn_merge_kernel(const float* __restrict__ in0,
                                 const float* __restrict__ in1,
                                 float* __restrict__ out_xyz, int write_xyz) {
    int g = blockIdx.x * 256 + threadIdx.x;
    int b = g / N2;

    float e0 = CUDART_INF_F, e1 = CUDART_INF_F, e2 = CUDART_INF_F;
    int i0 = 0, i1 = 0, i2 = 0;
    size_t base = (size_t)g * NSLICE * 3;
    #pragma unroll
    for (int t = 0; t < NSLICE * 3; t++) {
        float d = g_pd[base + t];
        int   j = g_pi[base + t];
        TOP3_UPDATE(d, e0, e1, e2, i0, i1, i2, j);
    }

    const float* q = in1 + (size_t)g * IN1S;
    float qx = q[0], qy = q[1], qz = q[2];

    const float* P = in0 + (size_t)(b * N1) * IN0S;
    const float* p = P + (size_t)i0 * IN0S;
    float dx = p[0] - qx, dy = p[1] - qy, dz = p[2] - qz;
    float d0 = fmaxf(fmaf(dx, dx, fmaf(dy, dy, dz * dz)), KEPS);
    p = P + (size_t)i1 * IN0S;
    dx = p[0] - qx; dy = p[1] - qy; dz = p[2] - qz;
    float d1 = fmaxf(fmaf(dx, dx, fmaf(dy, dy, dz * dz)), KEPS);
    p = P + (size_t)i2 * IN0S;
    dx = p[0] - qx; dy = p[1] - qy; dz = p[2] - qz;
    float d2 = fmaxf(fmaf(dx, dx, fmaf(dy, dy, dz * dz)), KEPS);

    float w0 = 1.f / d0, w1 = 1.f / d1, w2 = 1.f / d2;
    float inv = 1.f / (w0 + w1 + w2);
    g_idx[g * 3 + 0] = i0; g_idx[g * 3 + 1] = i1; g_idx[g * 3 + 2] = i2;
    g_w[g * 3 + 0] = w0 * inv; g_w[g * 3 + 1] = w1 * inv; g_w[g * 3 + 2] = w2 * inv;
    if (write_xyz) {
        out_xyz[(size_t)g * 3 + 0] = qx;
        out_xyz[(size_t)g * 3 + 1] = qy;
        out_xyz[(size_t)g * 3 + 2] = qz;
    }
}

// ---------------------------------------------------------------------------
// K2: fused MLP v7 — HMMA bf16 hi/lo, 512 threads / 16 warps.
// Warp (rw = wid&7, nh = wid>>3): rows rw*16..+15, column half nh*64..+63.
// Per-warp MMA+B-LDS halve vs v6; warps/SMSP double (2->4).
// ---------------------------------------------------------------------------
__global__ void __launch_bounds__(512, 1)
mlp_kernel(const float* __restrict__ in1, const float* __restrict__ W1,
           const float* __restrict__ b1, const float* __restrict__ W2,
           const float* __restrict__ b2, float* __restrict__ out) {
    extern __shared__ __align__(16) char smc[];
    float* sH  = (float*)(smc + SH_B);
    float* sB1 = (float*)(smc + B1_B);
    float* sB2 = (float*)(smc + B2_B);
    unsigned short* sAhi = (unsigned short*)(smc + AHI_B);
    unsigned short* sAlo = (unsigned short*)(smc + ALO_B);
    unsigned short* sW1hi = (unsigned short*)(smc + W1HI_B);
    unsigned short* sW1lo = (unsigned short*)(smc + W1LO_B);
    unsigned short* sW2hi = (unsigned short*)(smc + W2HI_B);
    unsigned short* sW2lo = (unsigned short*)(smc + W2LO_B);
    unsigned short* sHhi = (unsigned short*)(smc + HHI_B);
    unsigned short* sHlo = (unsigned short*)(smc + HLO_B);

    int tid = threadIdx.x;
    int wid = tid >> 5, lane = tid & 31;
    int gq = lane >> 2, tg = lane & 3;       // quad row / thread-in-quad
    int rw = wid & 7, nh = wid >> 3;         // row group / column half
    int g0 = blockIdx.x * 128;
    int bb = g0 / N2;

    // ---- prologue: bf16 hi/lo conversions into smem ----
    for (int idx = tid; idx < 8192; idx += 512) {        // A: (m=128, c=64)
        int m = idx >> 6, c = idx & 63;
        float v = in1[(size_t)(g0 + m) * IN1S + 3 + c];
        __nv_bfloat16 h = __float2bfloat16(v);
        __nv_bfloat16 l = __float2bfloat16(v - __bfloat162float(h));
        sAhi[m * ASTB + c] = __bfloat16_as_ushort(h);
        sAlo[m * ASTB + c] = __bfloat16_as_ushort(l);
    }
    for (int idx = tid; idx < 8192; idx += 512) {        // W1b^T: (n=128, k=64)
        int n = idx & 127, k = idx >> 7;
        float v = W1[(size_t)(C1 + k) * F1 + n];
        __nv_bfloat16 h = __float2bfloat16(v);
        __nv_bfloat16 l = __float2bfloat16(v - __bfloat162float(h));
        sW1hi[n * ASTB + k] = __bfloat16_as_ushort(h);
        sW1lo[n * ASTB + k] = __bfloat16_as_ushort(l);
    }
    for (int idx = tid; idx < 16384; idx += 512) {       // W2^T: (n=128, k=128)
        int n = idx & 127, k = idx >> 7;
        float v = W2[(size_t)k * F2 + n];
        __nv_bfloat16 h = __float2bfloat16(v);
        __nv_bfloat16 l = __float2bfloat16(v - __bfloat162float(h));
        sW2hi[n * HSTB + k] = __bfloat16_as_ushort(h);
        sW2lo[n * HSTB + k] = __bfloat16_as_ushort(l);
    }
    if (tid < 128) { sB1[tid] = b1[tid]; sB2[tid] = b2[tid]; }
    __syncthreads();

    // ---- gather interpolation (+b1) -> sH fp32 (4 threads per query row) ----
    {
        int m  = tid >> 2;
        int fo = (tid & 3) * 32;
        int g  = g0 + m;
        int j0 = g_idx[g * 3 + 0], j1 = g_idx[g * 3 + 1], j2 = g_idx[g * 3 + 2];
        float w0 = g_w[g * 3 + 0], w1 = g_w[g * 3 + 1], w2 = g_w[g * 3 + 2];
        const float* Pg = g_PW + (size_t)bb * N1 * F1;
        const float* p0 = Pg + (size_t)j0 * F1;
        const float* p1 = Pg + (size_t)j1 * F1;
        const float* p2 = Pg + (size_t)j2 * F1;
        #pragma unroll
        for (int u = 0; u < 32; u += 4) {
            int f = fo + u;
            float4 a  = *(const float4*)(p0 + f);
            float4 c4 = *(const float4*)(p1 + f);
            float4 e4 = *(const float4*)(p2 + f);
            float4 bv = *(const float4*)(sB1 + f);
            float4 r;
            r.x = bv.x + w0 * a.x + w1 * c4.x + w2 * e4.x;
            r.y = bv.y + w0 * a.y + w1 * c4.y + w2 * e4.y;
            r.z = bv.z + w0 * a.z + w1 * c4.z + w2 * e4.z;
            r.w = bv.w + w0 * a.w + w1 * c4.w + w2 * e4.w;
            *(float4*)(sH + m * HST + f) = r;
        }
    }
    __syncthreads();

    int r0 = rw * 16 + gq;                   // fragment rows r0, r0+8

    // ---- GEMM1 accum init from sH (interp + b1), this warp's column half ----
    float c[8][4];
    #pragma unroll
    for (int nt = 0; nt < 8; nt++) {
        int n0 = (nh * 8 + nt) * 8 + 2 * tg;
        float2 v0 = *(const float2*)(sH + r0 * HST + n0);
        float2 v1 = *(const float2*)(sH + (r0 + 8) * HST + n0);
        c[nt][0] = v0.x; c[nt][1] = v0.y;
        c[nt][2] = v1.x; c[nt][3] = v1.y;
    }
    __syncthreads();   // all sH reads complete (region reused for H bf16)

    // ---- GEMM1: A(128x64) @ W1b(64x128) via HMMA, K=64 -> 4 k-steps ----
    #pragma unroll
    for (int ks = 0; ks < 4; ks++) {
        int ka = ks * 16 + 2 * tg;
        uint32_t ah0 = *(const uint32_t*)(sAhi + r0 * ASTB + ka);
        uint32_t ah1 = *(const uint32_t*)(sAhi + (r0 + 8) * ASTB + ka);
        uint32_t ah2 = *(const uint32_t*)(sAhi + r0 * ASTB + ka + 8);
        uint32_t ah3 = *(const uint32_t*)(sAhi + (r0 + 8) * ASTB + ka + 8);
        uint32_t al0 = *(const uint32_t*)(sAlo + r0 * ASTB + ka);
        uint32_t al1 = *(const uint32_t*)(sAlo + (r0 + 8) * ASTB + ka);
        uint32_t al2 = *(const uint32_t*)(sAlo + r0 * ASTB + ka + 8);
        uint32_t al3 = *(const uint32_t*)(sAlo + (r0 + 8) * ASTB + ka + 8);
        #pragma unroll
        for (int nt = 0; nt < 8; nt++) {
            int nr = (nh * 8 + nt) * 8 + gq;
            uint32_t bh0 = *(const uint32_t*)(sW1hi + nr * ASTB + ka);
            uint32_t bh1 = *(const uint32_t*)(sW1hi + nr * ASTB + ka + 8);
            uint32_t bl0 = *(const uint32_t*)(sW1lo + nr * ASTB + ka);
            uint32_t bl1 = *(const uint32_t*)(sW1lo + nr * ASTB + ka + 8);
            MMA_BF16(c[nt], ah0, ah1, ah2, ah3, bh0, bh1);
            MMA_BF16(c[nt], ah0, ah1, ah2, ah3, bl0, bl1);
            MMA_BF16(c[nt], al0, al1, al2, al3, bh0, bh1);
        }
    }

    // ---- relu + hi/lo split -> H bf16 (aliases dead sH region) ----
    #pragma unroll
    for (int nt = 0; nt < 8; nt++) {
        int n0 = (nh * 8 + nt) * 8 + 2 * tg;
        uint32_t lo;
        uint32_t hi = pack_bf16_hi2(fmaxf(c[nt][0], 0.f), fmaxf(c[nt][1], 0.f), &lo);
        *(uint32_t*)(sHhi + r0 * HSTB + n0) = hi;
        *(uint32_t*)(sHlo + r0 * HSTB + n0) = lo;
        hi = pack_bf16_hi2(fmaxf(c[nt][2], 0.f), fmaxf(c[nt][3], 0.f), &lo);
        *(uint32_t*)(sHhi + (r0 + 8) * HSTB + n0) = hi;
        *(uint32_t*)(sHlo + (r0 + 8) * HSTB + n0) = lo;
    }
    __syncthreads();

    // ---- GEMM2: H(128x128) @ W2(128x128) via HMMA, K=128 -> 8 k-steps ----
    #pragma unroll
    for (int nt = 0; nt < 8; nt++) {
        c[nt][0] = 0.f; c[nt][1] = 0.f; c[nt][2] = 0.f; c[nt][3] = 0.f;
    }
    #pragma unroll
    for (int ks = 0; ks < 8; ks++) {
        int ka = ks * 16 + 2 * tg;
        uint32_t ah0 = *(const uint32_t*)(sHhi + r0 * HSTB + ka);
        uint32_t ah1 = *(const uint32_t*)(sHhi + (r0 + 8) * HSTB + ka);
        uint32_t ah2 = *(const uint32_t*)(sHhi + r0 * HSTB + ka + 8);
        uint32_t ah3 = *(const uint32_t*)(sHhi + (r0 + 8) * HSTB + ka + 8);
        uint32_t al0 = *(const uint32_t*)(sHlo + r0 * HSTB + ka);
        uint32_t al1 = *(const uint32_t*)(sHlo + (r0 + 8) * HSTB + ka);
        uint32_t al2 = *(const uint32_t*)(sHlo + r0 * HSTB + ka + 8);
        uint32_t al3 = *(const uint32_t*)(sHlo + (r0 + 8) * HSTB + ka + 8);
        #pragma unroll
        for (int nt = 0; nt < 8; nt++) {
            int nr = (nh * 8 + nt) * 8 + gq;
            uint32_t bh0 = *(const uint32_t*)(sW2hi + nr * HSTB + ka);
            uint32_t bh1 = *(const uint32_t*)(sW2hi + nr * HSTB + ka + 8);
            uint32_t bl0 = *(const uint32_t*)(sW2lo + nr * HSTB + ka);
            uint32_t bl1 = *(const uint32_t*)(sW2lo + nr * HSTB + ka + 8);
            MMA_BF16(c[nt], ah0, ah1, ah2, ah3, bh0, bh1);
            MMA_BF16(c[nt], ah0, ah1, ah2, ah3, bl0, bl1);
            MMA_BF16(c[nt], al0, al1, al2, al3, bh0, bh1);
        }
    }

    // ---- epilogue: +b2, relu, store ----
    #pragma unroll
    for (int nt = 0; nt < 8; nt++) {
        int n0 = (nh * 8 + nt) * 8 + 2 * tg;
        float2 bv = *(const float2*)(sB2 + n0);
        float2 v0, v1;
        v0.x = fmaxf(c[nt][0] + bv.x, 0.f);
        v0.y = fmaxf(c[nt][1] + bv.y, 0.f);
        v1.x = fmaxf(c[nt][2] + bv.x, 0.f);
        v1.y = fmaxf(c[nt][3] + bv.y, 0.f);
        *(float2*)(out + (size_t)(g0 + r0) * F2 + n0) = v0;
        *(float2*)(out + (size_t)(g0 + r0 + 8) * F2 + n0) = v1;
    }
}

// ---------------------------------------------------------------------------
extern "C" void kernel_launch(void* const* d_in, const int* in_sizes, int n_in,
                              void* d_out, int out_size) {
    const float* in0 = (const float*)d_in[0];   // inputs0 (B, N1, 131)
    const float* in1 = (const float*)d_in[1];   // inputs1 (B, N2, 67)
    const float* W1  = (const float*)d_in[2];   // (192, 128)
    const float* b1  = (const float*)d_in[3];   // (128,)
    const float* W2  = (const float*)d_in[4];   // (128, 128)
    const float* b2  = (const float*)d_in[5];   // (128,)
    float* out = (float*)d_out;

    const int x_elems = BATCH * N2 * F2;                 // 8,388,608
    int write_xyz = (out_size >= x_elems + BATCH * N2 * 3) ? 1 : 0;

    cudaFuncSetAttribute(mlp_kernel, cudaFuncAttributeMaxDynamicSharedMemorySize,
                         MLP_SMEM_B);

    knn_part_kernel<<<dim3(N2 / 512, NSLICE, BATCH), 256>>>(in0, in1);
    pw_kernel<<<(BATCH * N1) / 8, 128>>>(in0, W1);
    knn_merge_kernel<<<(BATCH * N2) / 256, 256>>>(in0, in1, out + x_elems, write_xyz);
    mlp_kernel<<<(BATCH * N2) / 128, 512, MLP_SMEM_B>>>(in1, W1, b1, W2, b2, out);
}